// round 11
// baseline (speedup 1.0000x reference)
#include <cuda_runtime.h>
#include <cstdint>

#define NN 5000
#define BT 128
#define HPD 68           // half-tile row stride (floats): 16B-aligned, conflict-free
#define SPD 132          // S row stride
#define NPAD 5120
#define NTHREADS 256
#define NMAT 12
#define NHALF (2 * NMAT)
#define SLOT (BT * HPD)  // floats per half-tile slot

__device__ float g_St[2][16][NPAD];   // transposed supports; pad rows zero

// ---------------- helpers ----------------
__device__ __forceinline__ uint32_t f2tf32(float x) {
    uint32_t r;
    asm("cvt.rna.tf32.f32 %0, %1;" : "=r"(r) : "f"(x));
    return r;
}
__device__ __forceinline__ void mma_tf32(float* d, float a0, float a1,
                                         float a2, float a3,
                                         uint32_t b0, uint32_t b1) {
    asm volatile(
        "mma.sync.aligned.m16n8k8.row.col.f32.tf32.tf32.f32 "
        "{%0,%1,%2,%3}, {%4,%5,%6,%7}, {%8,%9}, {%0,%1,%2,%3};"
        : "+f"(d[0]), "+f"(d[1]), "+f"(d[2]), "+f"(d[3])
        : "r"(__float_as_uint(a0)), "r"(__float_as_uint(a1)),
          "r"(__float_as_uint(a2)), "r"(__float_as_uint(a3)),
          "r"(b0), "r"(b1));
}
__device__ __forceinline__ void red_add_v2(float* p, float x, float y) {
    asm volatile("red.global.add.v2.f32 [%0], {%1, %2};"
                 :: "l"(p), "f"(x), "f"(y) : "memory");
}
__device__ __forceinline__ void cp_async16(uint32_t dst, const void* src, int sz) {
    asm volatile("cp.async.cg.shared.global [%0], [%1], 16, %2;"
                 :: "r"(dst), "l"(src), "r"(sz));
}
__device__ __forceinline__ void cp_commit() { asm volatile("cp.async.commit_group;"); }
template <int N>
__device__ __forceinline__ void cp_wait() {
    asm volatile("cp.async.wait_group %0;" :: "n"(N) : "memory");
}

// ---------------- prep: g_St = (feature @ W)^T, bias-init out ----------------
__global__ void fame_prep(const float* __restrict__ feature,
                          const float* __restrict__ W3, const float* __restrict__ b3,
                          const float* __restrict__ W1, const float* __restrict__ b1,
                          float* __restrict__ out) {
    __shared__ float fsm[128];
    const int row = blockIdx.x;
    const int t = threadIdx.x;
    fsm[t] = feature[row * 128 + t];
    __syncthreads();
    if (t < 32) {
        const int g = t >> 4;
        const int c = t & 15;
        const float* __restrict__ W = g ? W1 : W3;
        float s = 0.f;
#pragma unroll 16
        for (int k = 0; k < 128; k++) s += fsm[k] * W[k * 16 + c];
        g_St[g][c][row] = s;
    } else if (t < 64) {
        const int c = t - 32;
        out[row * 32 + c] = (c < 16) ? b3[c] : b1[c - 16];
    }
}

// ------- main: half-tile double-buffer, 2 CTAs/SM, reg-B TF32 mma -------
__global__ __launch_bounds__(NTHREADS, 2)
void fame_main(const float* __restrict__ A, const float* __restrict__ At,
               const float* __restrict__ wA, const float* __restrict__ wB,
               float* __restrict__ out)
{
    extern __shared__ float smem[];
    float* S1u = smem + 2 * SLOT;            // [16][132] tf32 S^T rows j0..
    float* S2u = S1u + 16 * SPD;             // [16][132] tf32 S^T rows i0..

    const int t = threadIdx.x;
    const int wid = t >> 5, lane = t & 31;
    const int p = lane >> 2, q = lane & 3;
    const int side = wid >> 2;               // 0: direct GEMM, 1: transpose GEMM
    const int wsub = wid & 3;
    const int i0 = blockIdx.y * BT, j0 = blockIdx.x * BT;

    // ---- cp.async raw copy of half-tile ph into slot ph&1 ----
    auto issue_half = [&](int ph) {
        const int m = ph >> 1, h = ph & 1;
        const float* __restrict__ M = (m < 3)
            ? A  + (size_t)m       * (size_t)NN * (size_t)NN
            : At + (size_t)(m - 3) * (size_t)NN * (size_t)NN;
        const uint32_t sbase =
            (uint32_t)__cvta_generic_to_shared(smem + (ph & 1) * SLOT);
#pragma unroll
        for (int k = 0; k < 8; k++) {
            const int idx = t + NTHREADS * k;     // 0..2047
            const int row = idx >> 4;             // 0..127
            const int c = idx & 15;               // 16B chunk within 64 cols
            const int gi = i0 + row;
            const int gj = j0 + 64 * h + 4 * c;
            int sz = 0;
            if (gi < NN) {
                const int rem = (NN - gj) * 4;
                sz = rem >= 16 ? 16 : (rem > 0 ? rem : 0);
            }
            const float* src = M + (size_t)(gi < NN ? gi : 0) * NN
                                 + (gj < NN ? gj : 0);
            cp_async16(sbase + (uint32_t)(row * HPD + 4 * c) * 4u, src, sz);
        }
        cp_commit();
    };

    // ---- stage unscaled tf32 S^T tiles for group g (twice total) ----
    auto stage_S = [&](int g) {
#pragma unroll
        for (int it = 0; it < 16; it++) {
            const int idx = t + NTHREADS * it;    // 0..4095
            const int half = idx >> 11;
            const int n = (idx >> 7) & 15, k = idx & 127;
            const float v = g_St[g][n][(half ? i0 : j0) + k];
            (half ? S2u : S1u)[n * SPD + k] = __uint_as_float(f2tf32(v));
        }
    };

    uint32_t breg[64];
    auto load_B = [&]() {
        const float* __restrict__ Bp = (side ? S2u : S1u) + p * SPD + q;
#pragma unroll
        for (int ks = 0; ks < 16; ks++) {
            const int kb = 8 * ks;
            breg[4 * ks + 0] = __float_as_uint(Bp[kb]);
            breg[4 * ks + 1] = __float_as_uint(Bp[kb + 4]);
            breg[4 * ks + 2] = __float_as_uint(Bp[8 * SPD + kb]);
            breg[4 * ks + 3] = __float_as_uint(Bp[8 * SPD + kb + 4]);
        }
    };

    float acc[16];
#pragma unroll
    for (int a = 0; a < 16; a++) acc[a] = 0.f;

    auto flush = [&](int goff) {
#pragma unroll
        for (int blk = 0; blk < 2; blk++) {     // side0: rg; side1: half hh
            const int base_row = (side == 0) ? (i0 + 32 * wsub + 16 * blk)
                                             : (j0 + 64 * blk + 16 * wsub);
#pragma unroll
            for (int ng = 0; ng < 2; ng++) {
                float* ap = acc + blk * 8 + ng * 4;
                const int col = goff + 8 * ng + 2 * q;
                const int r0 = base_row + p;
                if (r0 < NN)     red_add_v2(out + (size_t)r0 * 32 + col, ap[0], ap[1]);
                if (r0 + 8 < NN) red_add_v2(out + (size_t)(r0 + 8) * 32 + col, ap[2], ap[3]);
            }
        }
#pragma unroll
        for (int a = 0; a < 16; a++) acc[a] = 0.f;
    };

    // ---- prologue ----
    issue_half(0);
    stage_S(0);

    for (int ph = 0; ph < NHALF; ph++) {
        const int m = ph >> 1, h = ph & 1;

        if (ph + 1 < NHALF) issue_half(ph + 1);   // slot safety: trailing bar of prev iter
        if (ph + 1 < NHALF) { cp_wait<1>(); } else { cp_wait<0>(); }
        __syncthreads();                           // half ph resident & visible

        if (ph == 0) load_B();
        if (ph == 6) {                             // group switch (m=3, h=0)
            stage_S(1);
            __syncthreads();
            load_B();
        }

        const float* __restrict__ Tb = smem + (ph & 1) * SLOT;
        const float w = (m < 3) ? wA[m] : wB[m - 3];

        if (side == 0) {
            // out rows i0+32wsub .. +32; local cols (j) = K, global ks = 8h+ks
            const float* __restrict__ Ta = Tb + (32 * wsub + p) * HPD + q;
#pragma unroll
            for (int ks = 0; ks < 8; ks++) {
                const int kb = 8 * ks;
                const int kg = 4 * (8 * h + ks);
                const float a00 = w * Ta[kb];
                const float a01 = w * Ta[8 * HPD + kb];
                const float a02 = w * Ta[kb + 4];
                const float a03 = w * Ta[8 * HPD + kb + 4];
                const float a10 = w * Ta[16 * HPD + kb];
                const float a11 = w * Ta[24 * HPD + kb];
                const float a12 = w * Ta[16 * HPD + kb + 4];
                const float a13 = w * Ta[24 * HPD + kb + 4];
                mma_tf32(acc + 0,  a00, a01, a02, a03, breg[kg + 0], breg[kg + 1]);
                mma_tf32(acc + 4,  a00, a01, a02, a03, breg[kg + 2], breg[kg + 3]);
                mma_tf32(acc + 8,  a10, a11, a12, a13, breg[kg + 0], breg[kg + 1]);
                mma_tf32(acc + 12, a10, a11, a12, a13, breg[kg + 2], breg[kg + 3]);
            }
        } else {
            // out rows j0+64h+16wsub..+16 (acc block h); K = 128 tile rows (i)
            const float* __restrict__ Tt = Tb + 16 * wsub + p;
            float* __restrict__ acch = acc + 8 * h;
#pragma unroll
            for (int ks = 0; ks < 16; ks++) {
                const int kb = 8 * ks;
                const float* __restrict__ Tc = Tt + (kb + q) * HPD;
                const float a0 = w * Tc[0];
                const float a1 = w * Tc[8];
                const float a2 = w * Tc[4 * HPD];
                const float a3 = w * Tc[4 * HPD + 8];
                mma_tf32(acch,     a0, a1, a2, a3, breg[4 * ks + 0], breg[4 * ks + 1]);
                mma_tf32(acch + 4, a0, a1, a2, a3, breg[4 * ks + 2], breg[4 * ks + 3]);
            }
        }

        if (ph == 5) flush(0);              // group A -> cols 0..15
        if (ph == NHALF - 1) flush(16);     // group B -> cols 16..31

        __syncthreads();                    // all done with slot ph&1 before refill
    }
}

extern "C" void kernel_launch(void* const* d_in, const int* in_sizes, int n_in,
                              void* d_out, int out_size) {
    const float* feature = (const float*)d_in[0];  // [5000,128]
    const float* A       = (const float*)d_in[1];  // [3,5000,5000]
    const float* At      = (const float*)d_in[2];  // [9,5000,5000]
    const float* wb2     = (const float*)d_in[3];  // [3,1]
    const float* wb      = (const float*)d_in[4];  // [9,1]
    const float* W3      = (const float*)d_in[5];  // [128,16]
    const float* b3      = (const float*)d_in[6];  // [16]
    const float* W1      = (const float*)d_in[7];  // [128,16]
    const float* b1      = (const float*)d_in[8];  // [16]
    float* out = (float*)d_out;                    // [5000,32]

    fame_prep<<<NN, 128>>>(feature, W3, b3, W1, b1, out);

    const int smem_bytes = (2 * SLOT + 2 * 16 * SPD) * (int)sizeof(float);
    cudaFuncSetAttribute(fame_main, cudaFuncAttributeMaxDynamicSharedMemorySize, smem_bytes);
    dim3 grid((NN + BT - 1) / BT, (NN + BT - 1) / BT);
    fame_main<<<grid, NTHREADS, smem_bytes>>>(A, At, wb2, wb, out);
}

// round 12
// speedup vs baseline: 1.4809x; 1.4809x over previous
#include <cuda_runtime.h>
#include <cstdint>

#define NN 5000
#define BT 128
#define TPD 132          // T row stride (floats), 16B-aligned, conflict-free
#define SPD 132          // S row stride
#define NPAD 5120
#define NTHREADS 512
#define NMAT 12
#define SLOT (BT * TPD)  // floats per tile slot

__device__ float g_St[2][16][NPAD];   // transposed supports; pad rows zero

// ---------------- helpers ----------------
__device__ __forceinline__ uint32_t f2tf32(float x) {
    uint32_t r;
    asm("cvt.rna.tf32.f32 %0, %1;" : "=r"(r) : "f"(x));
    return r;
}
__device__ __forceinline__ void mma_tf32(float* d, uint32_t a0, uint32_t a1,
                                         uint32_t a2, uint32_t a3,
                                         uint32_t b0, uint32_t b1) {
    asm volatile(
        "mma.sync.aligned.m16n8k8.row.col.f32.tf32.tf32.f32 "
        "{%0,%1,%2,%3}, {%4,%5,%6,%7}, {%8,%9}, {%0,%1,%2,%3};"
        : "+f"(d[0]), "+f"(d[1]), "+f"(d[2]), "+f"(d[3])
        : "r"(a0), "r"(a1), "r"(a2), "r"(a3), "r"(b0), "r"(b1));
}
__device__ __forceinline__ void red_add_v2(float* p, float x, float y) {
    asm volatile("red.global.add.v2.f32 [%0], {%1, %2};"
                 :: "l"(p), "f"(x), "f"(y) : "memory");
}
__device__ __forceinline__ void mbar_init(uint32_t mbar, uint32_t cnt) {
    asm volatile("mbarrier.init.shared.b64 [%0], %1;"
                 :: "r"(mbar), "r"(cnt) : "memory");
}
__device__ __forceinline__ void mbar_expect_tx(uint32_t mbar, uint32_t bytes) {
    asm volatile("mbarrier.arrive.expect_tx.shared.b64 _, [%0], %1;"
                 :: "r"(mbar), "r"(bytes) : "memory");
}
__device__ __forceinline__ void bulk_g2s(uint32_t dst, const void* src,
                                         uint32_t bytes, uint32_t mbar) {
    asm volatile(
        "cp.async.bulk.shared::cta.global.mbarrier::complete_tx::bytes "
        "[%0], [%1], %2, [%3];"
        :: "r"(dst), "l"(src), "r"(bytes), "r"(mbar) : "memory");
}
__device__ __forceinline__ void mbar_wait(uint32_t mbar, uint32_t parity) {
    uint32_t done;
    asm volatile(
        "{\n\t.reg .pred p;\n\t"
        "mbarrier.try_wait.parity.acquire.cta.shared::cta.b64 p, [%1], %2;\n\t"
        "selp.b32 %0, 1, 0, p;\n\t}"
        : "=r"(done) : "r"(mbar), "r"(parity) : "memory");
    if (!done) {
        asm volatile(
            "{\n\t.reg .pred P1;\n\t"
            "WAIT_LOOP_%=:\n\t"
            "mbarrier.try_wait.parity.acquire.cta.shared::cta.b64 P1, [%0], %1, 0x989680;\n\t"
            "@P1 bra.uni WAIT_DONE_%=;\n\t"
            "bra.uni WAIT_LOOP_%=;\n\t"
            "WAIT_DONE_%=:\n\t}"
            :: "r"(mbar), "r"(parity) : "memory");
    }
}

// ---------------- prep: g_St = (feature @ W)^T, bias-init out ----------------
__global__ void fame_prep(const float* __restrict__ feature,
                          const float* __restrict__ W3, const float* __restrict__ b3,
                          const float* __restrict__ W1, const float* __restrict__ b1,
                          float* __restrict__ out) {
    __shared__ float fsm[128];
    const int row = blockIdx.x;
    const int t = threadIdx.x;
    fsm[t] = feature[row * 128 + t];
    __syncthreads();
    if (t < 32) {
        const int g = t >> 4;
        const int c = t & 15;
        const float* __restrict__ W = g ? W1 : W3;
        float s = 0.f;
#pragma unroll 16
        for (int k = 0; k < 128; k++) s += fsm[k] * W[k * 16 + c];
        g_St[g][c][row] = s;
    } else if (t < 64) {
        const int c = t - 32;
        out[row * 32 + c] = (c < 16) ? b3[c] : b1[c - 16];
    }
}

// ------ main: 3-slot ring fed by cp.async.bulk rows, reg-B TF32 mma ------
__global__ __launch_bounds__(NTHREADS, 1)
void fame_main(const float* __restrict__ A, const float* __restrict__ At,
               const float* __restrict__ wA, const float* __restrict__ wB,
               float* __restrict__ out)
{
    extern __shared__ float smem[];
    float* S1u = smem + 3 * SLOT;            // [16][132] tf32 S^T rows j0..
    float* S2u = S1u + 16 * SPD;             // [16][132] tf32 S^T rows i0..
    const uint32_t smem_base = (uint32_t)__cvta_generic_to_shared(smem);
    const uint32_t mbar0 = smem_base + (uint32_t)(3 * SLOT + 2 * 16 * SPD) * 4u;

    const int t = threadIdx.x;
    const int wid = t >> 5, lane = t & 31;
    const int p = lane >> 2, q = lane & 3;
    const int side = wid >> 3;               // 0: direct GEMM, 1: transpose GEMM
    const int wsub = wid & 7;                // 16-row slice within side
    const int i0 = blockIdx.y * BT, j0 = blockIdx.x * BT;
    const bool interior = (i0 + BT <= NN) && (j0 + BT <= NN);

    // ---- prologue: mbarriers + (edge only) zero-fill ring slots ----
    if (t < 3) mbar_init(mbar0 + 8u * (uint32_t)t, 128u);
    if (!interior) {
        for (int idx = t; idx < 3 * SLOT; idx += NTHREADS) smem[idx] = 0.f;
    }
    __syncthreads();

    // ---- bulk-copy tile m into slot m%3 (one 512B row per thread t<128) ----
    const uint32_t row_bytes = (uint32_t)((j0 + BT <= NN ? BT : (NN - j0)) * 4);
    auto issue_tile = [&](int m) {
        if (t < 128) {
            const float* __restrict__ M = (m < 3)
                ? A  + (size_t)m       * (size_t)NN * (size_t)NN
                : At + (size_t)(m - 3) * (size_t)NN * (size_t)NN;
            const int slot = m - (m / 3) * 3;
            const uint32_t mb = mbar0 + 8u * (uint32_t)slot;
            const int gi = i0 + t;
            const uint32_t sz = (gi < NN) ? row_bytes : 0u;
            mbar_expect_tx(mb, sz);
            if (sz) bulk_g2s(smem_base + (uint32_t)(slot * SLOT + t * TPD) * 4u,
                             M + (size_t)gi * NN + j0, sz, mb);
        }
    };

    // ---- stage unscaled tf32 S^T tiles for group g ----
    auto stage_S = [&](int g) {
#pragma unroll
        for (int it = 0; it < 8; it++) {
            const int idx = t + NTHREADS * it;    // 0..4095
            const int half = idx >> 11;
            const int n = (idx >> 7) & 15, k = idx & 127;
            const float v = g_St[g][n][(half ? i0 : j0) + k];
            (half ? S2u : S1u)[n * SPD + k] = __uint_as_float(f2tf32(v));
        }
    };

    uint32_t breg[64];
    auto load_B = [&]() {
        const float* __restrict__ Bp = (side ? S2u : S1u) + p * SPD + q;
#pragma unroll
        for (int ks = 0; ks < 16; ks++) {
            const int kb = 8 * ks;
            breg[4 * ks + 0] = __float_as_uint(Bp[kb]);
            breg[4 * ks + 1] = __float_as_uint(Bp[kb + 4]);
            breg[4 * ks + 2] = __float_as_uint(Bp[8 * SPD + kb]);
            breg[4 * ks + 3] = __float_as_uint(Bp[8 * SPD + kb + 4]);
        }
    };

    float acc[8], araw[8];
#pragma unroll
    for (int a = 0; a < 8; a++) { acc[a] = 0.f; araw[a] = 0.f; }

    auto flush = [&](int goff) {
        const int base_row = ((side == 0) ? i0 : j0) + 16 * wsub;
#pragma unroll
        for (int ng = 0; ng < 2; ng++) {
            float* ap = acc + 4 * ng;
            const int col = goff + 8 * ng + 2 * q;
            const int r0 = base_row + p;
            if (r0 < NN)     red_add_v2(out + (size_t)r0 * 32 + col, ap[0], ap[1]);
            if (r0 + 8 < NN) red_add_v2(out + (size_t)(r0 + 8) * 32 + col, ap[2], ap[3]);
        }
#pragma unroll
        for (int a = 0; a < 8; a++) acc[a] = 0.f;
    };

    // ---- two tiles in flight + group-0 S staged, B in regs ----
    issue_tile(0);
    issue_tile(1);
    stage_S(0);
    __syncthreads();
    load_B();

    for (int m = 0; m < NMAT; m++) {
        const int slot = m - (m / 3) * 3;
        mbar_wait(mbar0 + 8u * (uint32_t)slot, (uint32_t)((m / 3) & 1));
        __syncthreads();   // + all warps finished compute on tile m-1 (slot reuse safe)

        if (m + 2 < NMAT) issue_tile(m + 2);

        if (m == 3) {      // group switch: restage S (group-A compute all done)
            stage_S(1);
            __syncthreads();
            load_B();
        }

        const float* __restrict__ Tb = smem + slot * SLOT;
        const float w = (m < 3) ? wA[m] : wB[m - 3];

        if (side == 0) {
            const float* __restrict__ Ta = Tb + (16 * wsub + p) * TPD + q;
#pragma unroll
            for (int ks = 0; ks < 16; ks++) {
                const int kb = 8 * ks;
                const uint32_t a0 = __float_as_uint(Ta[kb]);           // HW f32->tf32 truncation
                const uint32_t a1 = __float_as_uint(Ta[8 * TPD + kb]);
                const uint32_t a2 = __float_as_uint(Ta[kb + 4]);
                const uint32_t a3 = __float_as_uint(Ta[8 * TPD + kb + 4]);
                mma_tf32(araw,     a0, a1, a2, a3, breg[4 * ks + 0], breg[4 * ks + 1]);
                mma_tf32(araw + 4, a0, a1, a2, a3, breg[4 * ks + 2], breg[4 * ks + 3]);
            }
        } else {
            const float* __restrict__ Tt = Tb + 16 * wsub + p;
#pragma unroll
            for (int ks = 0; ks < 16; ks++) {
                const int kb = 8 * ks;
                const float* __restrict__ Tc = Tt + (kb + q) * TPD;
                const uint32_t a0 = __float_as_uint(Tc[0]);
                const uint32_t a1 = __float_as_uint(Tc[8]);
                const uint32_t a2 = __float_as_uint(Tc[4 * TPD]);
                const uint32_t a3 = __float_as_uint(Tc[4 * TPD + 8]);
                mma_tf32(araw,     a0, a1, a2, a3, breg[4 * ks + 0], breg[4 * ks + 1]);
                mma_tf32(araw + 4, a0, a1, a2, a3, breg[4 * ks + 2], breg[4 * ks + 3]);
            }
        }

        // fold matrix weight into the running group accumulator
#pragma unroll
        for (int a = 0; a < 8; a++) { acc[a] = fmaf(w, araw[a], acc[a]); araw[a] = 0.f; }

        if (m == 2) flush(0);          // group A -> cols 0..15
        if (m == NMAT - 1) flush(16);  // group B -> cols 16..31
    }
}

extern "C" void kernel_launch(void* const* d_in, const int* in_sizes, int n_in,
                              void* d_out, int out_size) {
    const float* feature = (const float*)d_in[0];  // [5000,128]
    const float* A       = (const float*)d_in[1];  // [3,5000,5000]
    const float* At      = (const float*)d_in[2];  // [9,5000,5000]
    const float* wb2     = (const float*)d_in[3];  // [3,1]
    const float* wb      = (const float*)d_in[4];  // [9,1]
    const float* W3      = (const float*)d_in[5];  // [128,16]
    const float* b3      = (const float*)d_in[6];  // [16]
    const float* W1      = (const float*)d_in[7];  // [128,16]
    const float* b1      = (const float*)d_in[8];  // [16]
    float* out = (float*)d_out;                    // [5000,32]

    fame_prep<<<NN, 128>>>(feature, W3, b3, W1, b1, out);

    // 3 slots + 2 S tiles + 3 mbarriers (24 B)
    const int smem_bytes = (3 * SLOT + 2 * 16 * SPD) * (int)sizeof(float) + 24;
    cudaFuncSetAttribute(fame_main, cudaFuncAttributeMaxDynamicSharedMemorySize, smem_bytes);
    dim3 grid((NN + BT - 1) / BT, (NN + BT - 1) / BT);
    fame_main<<<grid, NTHREADS, smem_bytes>>>(A, At, wb2, wb, out);
}